// round 4
// baseline (speedup 1.0000x reference)
#include <cuda_runtime.h>

// RX gate on qubit 5 of a 12-qubit statevector, batch 4096.
// out_re[j] = c*sr[j] + s*si[j^64]
// out_im[j] = c*si[j] - s*sr[j^64]
// d_out layout: [out_re (4096*4096 floats) | out_im (4096*4096 floats)]
//
// Coalesced mapping (R1/R3): 128-element group = 32 float4s; lane w = t&15
// covers the low half (bit6=0) contiguously, partner at +16 float4s.
// R4: each thread processes TWO group-pairs — its group, and the group
// NGROUPS/2 away — keeping every warp access a contiguous 256B chunk while
// doubling per-thread MLP (8 front-batched 16B loads).

#define NELEM   (4096 * 4096)
#define NGROUPS (NELEM / 128)        // 131072 groups of 128 elements
#define NTHREADS (NELEM / 16)        // 1,048,576: 2 float4-pairs per thread

__global__ void __launch_bounds__(256)
rx_gate_kernel(const float4* __restrict__ sr4,
               const float4* __restrict__ si4,
               const float*  __restrict__ theta,
               float4* __restrict__ ore4,
               float4* __restrict__ oim4)
{
    int t = blockIdx.x * blockDim.x + threadIdx.x;

    float half = 0.5f * __ldg(theta);
    float s, c;
    sincosf(half, &s, &c);

    int grp = t >> 4;
    int w   = t & 15;
    int i0lo = grp * 32 + w;                       // pair 0: element bit6 = 0
    int i0hi = i0lo + 16;                          // pair 0: element ^ 64
    int i1lo = (grp + NGROUPS / 2) * 32 + w;       // pair 1, far half of array
    int i1hi = i1lo + 16;

    // Front-batch all 8 loads (128 B in flight per thread).
    float4 ar0 = sr4[i0lo];
    float4 br0 = sr4[i0hi];
    float4 ai0 = si4[i0lo];
    float4 bi0 = si4[i0hi];
    float4 ar1 = sr4[i1lo];
    float4 br1 = sr4[i1hi];
    float4 ai1 = si4[i1lo];
    float4 bi1 = si4[i1hi];

    float4 v;

    // ---- pair 0 ----
    v.x = fmaf(c, ar0.x, s * bi0.x); v.y = fmaf(c, ar0.y, s * bi0.y);
    v.z = fmaf(c, ar0.z, s * bi0.z); v.w = fmaf(c, ar0.w, s * bi0.w);
    __stcs(ore4 + i0lo, v);

    v.x = fmaf(c, br0.x, s * ai0.x); v.y = fmaf(c, br0.y, s * ai0.y);
    v.z = fmaf(c, br0.z, s * ai0.z); v.w = fmaf(c, br0.w, s * ai0.w);
    __stcs(ore4 + i0hi, v);

    v.x = fmaf(c, ai0.x, -s * br0.x); v.y = fmaf(c, ai0.y, -s * br0.y);
    v.z = fmaf(c, ai0.z, -s * br0.z); v.w = fmaf(c, ai0.w, -s * br0.w);
    __stcs(oim4 + i0lo, v);

    v.x = fmaf(c, bi0.x, -s * ar0.x); v.y = fmaf(c, bi0.y, -s * ar0.y);
    v.z = fmaf(c, bi0.z, -s * ar0.z); v.w = fmaf(c, bi0.w, -s * ar0.w);
    __stcs(oim4 + i0hi, v);

    // ---- pair 1 ----
    v.x = fmaf(c, ar1.x, s * bi1.x); v.y = fmaf(c, ar1.y, s * bi1.y);
    v.z = fmaf(c, ar1.z, s * bi1.z); v.w = fmaf(c, ar1.w, s * bi1.w);
    __stcs(ore4 + i1lo, v);

    v.x = fmaf(c, br1.x, s * ai1.x); v.y = fmaf(c, br1.y, s * ai1.y);
    v.z = fmaf(c, br1.z, s * ai1.z); v.w = fmaf(c, br1.w, s * ai1.w);
    __stcs(ore4 + i1hi, v);

    v.x = fmaf(c, ai1.x, -s * br1.x); v.y = fmaf(c, ai1.y, -s * br1.y);
    v.z = fmaf(c, ai1.z, -s * br1.z); v.w = fmaf(c, ai1.w, -s * br1.w);
    __stcs(oim4 + i1lo, v);

    v.x = fmaf(c, bi1.x, -s * ar1.x); v.y = fmaf(c, bi1.y, -s * ar1.y);
    v.z = fmaf(c, bi1.z, -s * ar1.z); v.w = fmaf(c, bi1.w, -s * ar1.w);
    __stcs(oim4 + i1hi, v);
}

extern "C" void kernel_launch(void* const* d_in, const int* in_sizes, int n_in,
                              void* d_out, int out_size)
{
    const float4* sr4   = (const float4*)d_in[0];
    const float4* si4   = (const float4*)d_in[1];
    const float*  theta = (const float*)d_in[2];

    float* out   = (float*)d_out;
    float4* ore4 = (float4*)out;
    float4* oim4 = (float4*)(out + NELEM);

    const int threads = 256;
    const int blocks  = NTHREADS / threads;   // 4096, exact
    rx_gate_kernel<<<blocks, threads>>>(sr4, si4, theta, ore4, oim4);
}